// round 7
// baseline (speedup 1.0000x reference)
#include <cuda_runtime.h>
#include <cuda_bf16.h>
#include <cstdint>

#define KC      32              // k elems per chunk
#define NCH     16              // 512 / 32
#define MT      64              // rows per CTA
#define STR     80              // smem row stride bytes (32 bf16 = 64B + 16 pad)
#define AH_OFF  0               // A hi:  64*80  = 5120
#define AL_OFF  5120
#define BH_OFF  10240           // B hi: 512*80 = 40960
#define BL_OFF  51200
#define STG_SZ  92160
#define STAGE0  6144            // after b1/gamma/beta (1536 floats)
#define SMEM_TOTAL (STAGE0 + 2 * STG_SZ)

__device__ unsigned short g_W1hi[512 * 512];
__device__ unsigned short g_W1lo[512 * 512];

__global__ void split_w_kernel(const float* __restrict__ W1) {
    int i = blockIdx.x * 256 + threadIdx.x;
    float v = W1[i];
    __nv_bfloat16 h = __float2bfloat16_rn(v);
    __nv_bfloat16 l = __float2bfloat16_rn(v - __bfloat162float(h));
    g_W1hi[i] = __bfloat16_as_ushort(h);
    g_W1lo[i] = __bfloat16_as_ushort(l);
}

__device__ __forceinline__ uint32_t smem_u32(const void* p) {
    uint32_t a;
    asm("{ .reg .u64 t; cvta.to.shared.u64 t, %1; cvt.u32.u64 %0, t; }" : "=r"(a) : "l"(p));
    return a;
}
__device__ __forceinline__ void ldsm4(uint32_t* r, uint32_t a) {
    asm volatile("ldmatrix.sync.aligned.m8n8.x4.shared.b16 {%0,%1,%2,%3}, [%4];"
                 : "=r"(r[0]), "=r"(r[1]), "=r"(r[2]), "=r"(r[3]) : "r"(a));
}
__device__ __forceinline__ void mma16816(float* c, const uint32_t* a, const uint32_t* b) {
    asm volatile("mma.sync.aligned.m16n8k16.row.col.f32.bf16.bf16.f32 "
                 "{%0,%1,%2,%3}, {%4,%5,%6,%7}, {%8,%9}, {%0,%1,%2,%3};"
                 : "+f"(c[0]), "+f"(c[1]), "+f"(c[2]), "+f"(c[3])
                 : "r"(a[0]), "r"(a[1]), "r"(a[2]), "r"(a[3]), "r"(b[0]), "r"(b[1]));
}
__device__ __forceinline__ void cp16(uint32_t dst, const void* src) {
    asm volatile("cp.async.ca.shared.global [%0], [%1], 16;"
                 :: "r"(dst), "l"(__cvta_generic_to_global(src)));
}
__device__ __forceinline__ void cv8(const float4& va, const float4& vb,
                                    uint32_t* hi, uint32_t* lo) {
    float v[8] = {va.x, va.y, va.z, va.w, vb.x, vb.y, vb.z, vb.w};
#pragma unroll
    for (int e = 0; e < 4; ++e) {
        __nv_bfloat16 h0 = __float2bfloat16_rn(v[2*e]);
        __nv_bfloat16 h1 = __float2bfloat16_rn(v[2*e+1]);
        __nv_bfloat16 l0 = __float2bfloat16_rn(v[2*e]   - __bfloat162float(h0));
        __nv_bfloat16 l1 = __float2bfloat16_rn(v[2*e+1] - __bfloat162float(h1));
        hi[e] = ((uint32_t)__bfloat16_as_ushort(h1) << 16) | __bfloat16_as_ushort(h0);
        lo[e] = ((uint32_t)__bfloat16_as_ushort(l1) << 16) | __bfloat16_as_ushort(l0);
    }
}

__global__ void __launch_bounds__(256, 1)
hmma_head(const float* __restrict__ x,  const float* __restrict__ b1,
          const float* __restrict__ gamma, const float* __restrict__ beta,
          const float* __restrict__ Wout, const float* __restrict__ bout,
          float* __restrict__ out) {
    extern __shared__ char sm[];
    const uint32_t sbase = smem_u32(sm);
    const int tid  = threadIdx.x;
    const int lane = tid & 31;
    const int wid  = tid >> 5;
    const int wm   = wid & 1;          // 2 M-warps
    const int wn   = wid >> 1;         // 4 N-warps
    const int rowbase = blockIdx.x * MT;

    float* bgb = (float*)sm;           // b1[512] gamma[512] beta[512]
    for (int i = tid; i < 512; i += 256) {
        bgb[i]        = b1[i];
        bgb[512 + i]  = gamma[i];
        bgb[1024 + i] = beta[i];
    }

    // this thread's A-load duty: row ar, k-quarter aq (8 floats)
    const int ar = tid >> 2, aq = tid & 3;
    const int arg = rowbase + ar;
    const float* xrow = x + (((size_t)((arg >> 9) * 513 + (arg & 511))) << 9) + aq * 8;

    // ---- prologue: chunk 0 into stage 0 ----
    {
        float4 xa = *(const float4*)(xrow);
        float4 xb = *(const float4*)(xrow + 4);
        uint32_t hi[4], lo[4];
        cv8(xa, xb, hi, lo);
        *(uint4*)(sm + STAGE0 + AH_OFF + ar * STR + aq * 16) = *(uint4*)hi;
        *(uint4*)(sm + STAGE0 + AL_OFF + ar * STR + aq * 16) = *(uint4*)lo;
#pragma unroll
        for (int it = 0; it < 16; ++it) {
            int idx = tid + it * 256;
            int v = idx >> 11, rem = idx & 2047, row = rem >> 2, q = rem & 3;
            const unsigned short* src = (v ? g_W1lo : g_W1hi) + row * 512 + q * 8;
            cp16(sbase + STAGE0 + (v ? BL_OFF : BH_OFF) + row * STR + q * 16, src);
        }
        asm volatile("cp.async.commit_group;");
        asm volatile("cp.async.wait_group 0;");
        __syncthreads();
    }

    float acc[2][16][4];
#pragma unroll
    for (int i = 0; i < 2; ++i)
#pragma unroll
        for (int j = 0; j < 16; ++j)
#pragma unroll
            for (int e = 0; e < 4; ++e) acc[i][j][e] = 0.f;

    const uint32_t aoff  = (uint32_t)((lane & 15) * STR + (lane >> 4) * 16) + wm * 32 * STR;
    // B ldsm4: m0/m1 = n-rows 0-7 (k0-7, k8-15); m2/m3 = n-rows 8-15
    const uint32_t b4off = (uint32_t)((lane & 7) * STR + ((lane >> 3) & 1) * 16
                                      + (lane >> 4) * 8 * STR) + wn * 128 * STR;

#pragma unroll 1
    for (int c = 0; c < NCH; ++c) {
        const uint32_t stg  = STAGE0 + (uint32_t)(c & 1) * STG_SZ;
        const uint32_t nstg = STAGE0 + (uint32_t)((c & 1) ^ 1) * STG_SZ;
        float4 nxa, nxb;
        if (c < NCH - 1) {
            const int k0n = (c + 1) * KC;
            nxa = *(const float4*)(xrow + k0n);
            nxb = *(const float4*)(xrow + k0n + 4);
#pragma unroll
            for (int it = 0; it < 16; ++it) {
                int idx = tid + it * 256;
                int v = idx >> 11, rem = idx & 2047, row = rem >> 2, q = rem & 3;
                const unsigned short* src = (v ? g_W1lo : g_W1hi) + row * 512 + k0n + q * 8;
                cp16(sbase + nstg + (v ? BL_OFF : BH_OFF) + row * STR + q * 16, src);
            }
            asm volatile("cp.async.commit_group;");
        }

        // ---- compute on stg: software-pipelined B fragments ----
#pragma unroll
        for (int ks = 0; ks < 2; ++ks) {
            uint32_t ah0[4], ah1[4], al0[4], al1[4];
            const uint32_t ab = sbase + stg + aoff + ks * 32;
            ldsm4(ah0, ab + AH_OFF);
            ldsm4(ah1, ab + AH_OFF + 16 * STR);
            ldsm4(al0, ab + AL_OFF);
            ldsm4(al1, ab + AL_OFF + 16 * STR);

            const uint32_t bb = sbase + stg + b4off + ks * 32;
            uint32_t bh[2][4], bl[2][4];
            ldsm4(bh[0], bb + BH_OFF);
            ldsm4(bl[0], bb + BL_OFF);
#pragma unroll
            for (int jj = 0; jj < 8; ++jj) {
                const int cur = jj & 1, nxt = cur ^ 1;
                if (jj < 7) {
                    const uint32_t bn = bb + (uint32_t)(jj + 1) * (16 * STR);
                    ldsm4(bh[nxt], bn + BH_OFF);
                    ldsm4(bl[nxt], bn + BL_OFF);
                }
                const int j0 = 2 * jj, j1 = 2 * jj + 1;
                // j0 uses frag regs 0-1, j1 uses 2-3
                mma16816(acc[0][j0], ah0, &bh[cur][0]);
                mma16816(acc[1][j0], ah1, &bh[cur][0]);
                mma16816(acc[0][j1], ah0, &bh[cur][2]);
                mma16816(acc[1][j1], ah1, &bh[cur][2]);
                mma16816(acc[0][j0], al0, &bh[cur][0]);
                mma16816(acc[1][j0], al1, &bh[cur][0]);
                mma16816(acc[0][j1], al0, &bh[cur][2]);
                mma16816(acc[1][j1], al1, &bh[cur][2]);
                mma16816(acc[0][j0], ah0, &bl[cur][0]);
                mma16816(acc[1][j0], ah1, &bl[cur][0]);
                mma16816(acc[0][j1], ah0, &bl[cur][2]);
                mma16816(acc[1][j1], ah1, &bl[cur][2]);
            }
        }

        if (c < NCH - 1) {
            uint32_t hi[4], lo[4];
            cv8(nxa, nxb, hi, lo);
            *(uint4*)(sm + nstg + AH_OFF + ar * STR + aq * 16) = *(uint4*)hi;
            *(uint4*)(sm + nstg + AL_OFF + ar * STR + aq * 16) = *(uint4*)lo;
        }
        asm volatile("cp.async.wait_group 0;");
        __syncthreads();
    }

    // ---- fused epilogue ----
    float2* stats = (float2*)(sm + STAGE0);          // [4][64]
    float2* munrs = (float2*)(sm + STAGE0 + 2048);   // [64]
    float*  pp    = (float*)(sm + STAGE0 + 2560);    // [4][64]

    float sums[4], ssqs[4];
#pragma unroll
    for (int idx = 0; idx < 4; ++idx) {
        const int i = idx >> 1, half = idx & 1;
        float s = 0.f, ss = 0.f;
#pragma unroll
        for (int j = 0; j < 16; ++j) {
            const int cc = wn * 128 + j * 8 + (lane & 3) * 2;
            float h0 = acc[i][j][half * 2 + 0] + bgb[cc];
            float h1 = acc[i][j][half * 2 + 1] + bgb[cc + 1];
            s += h0 + h1;
            ss += h0 * h0 + h1 * h1;
        }
        s  += __shfl_xor_sync(0xffffffffu, s, 1);  s  += __shfl_xor_sync(0xffffffffu, s, 2);
        ss += __shfl_xor_sync(0xffffffffu, ss, 1); ss += __shfl_xor_sync(0xffffffffu, ss, 2);
        sums[idx] = s; ssqs[idx] = ss;
    }
    if ((lane & 3) == 0) {
        const int q = lane >> 2;
#pragma unroll
        for (int idx = 0; idx < 4; ++idx) {
            const int r = wm * 32 + (idx >> 1) * 16 + (idx & 1) * 8 + q;
            stats[wn * 64 + r] = make_float2(sums[idx], ssqs[idx]);
        }
    }
    __syncthreads();
    if (tid < 64) {
        float s = 0.f, ss = 0.f;
#pragma unroll
        for (int w = 0; w < 4; ++w) { float2 v = stats[w * 64 + tid]; s += v.x; ss += v.y; }
        const float mu = s * (1.f / 512.f);
        const float var = ss * (1.f / 512.f) - mu * mu;
        munrs[tid] = make_float2(mu, rsqrtf(var + 1e-5f));
    }
    __syncthreads();

#pragma unroll
    for (int idx = 0; idx < 4; ++idx) {
        const int i = idx >> 1, half = idx & 1;
        const int r = wm * 32 + (idx >> 1) * 16 + (idx & 1) * 8 + (lane >> 2);
        const float2 mr = munrs[r];
        const int tt = (rowbase + r) & 511;
        const float* wrow = Wout + (((size_t)tt) << 9);
        float p = 0.f;
#pragma unroll
        for (int j = 0; j < 16; ++j) {
            const int cc = wn * 128 + j * 8 + (lane & 3) * 2;
            const float2 wo = *(const float2*)(wrow + cc);
            float h0 = acc[i][j][half * 2 + 0] + bgb[cc];
            float h1 = acc[i][j][half * 2 + 1] + bgb[cc + 1];
            float y0 = fmaxf((h0 - mr.x) * mr.y * bgb[512 + cc]     + bgb[1024 + cc],     0.f);
            float y1 = fmaxf((h1 - mr.x) * mr.y * bgb[512 + cc + 1] + bgb[1024 + cc + 1], 0.f);
            p += y0 * wo.x + y1 * wo.y;
        }
        p += __shfl_xor_sync(0xffffffffu, p, 1);
        p += __shfl_xor_sync(0xffffffffu, p, 2);
        if ((lane & 3) == 0) pp[wn * 64 + r] = p;
    }
    __syncthreads();
    if (tid < 64) {
        const int rg = rowbase + tid;
        const int tt = rg & 511;
        out[rg] = pp[tid] + pp[64 + tid] + pp[128 + tid] + pp[192 + tid] + bout[tt];
    }
}

extern "C" void kernel_launch(void* const* d_in, const int* in_sizes, int n_in,
                              void* d_out, int out_size) {
    const float* x     = (const float*)d_in[0];
    const float* W1    = (const float*)d_in[1];
    const float* b1    = (const float*)d_in[2];
    const float* gamma = (const float*)d_in[3];
    const float* beta  = (const float*)d_in[4];
    const float* Wout  = (const float*)d_in[5];
    const float* bout  = (const float*)d_in[6];
    float* out = (float*)d_out;

    cudaFuncSetAttribute(hmma_head, cudaFuncAttributeMaxDynamicSharedMemorySize, SMEM_TOTAL);

    split_w_kernel<<<1024, 256>>>(W1);
    hmma_head<<<131072 / MT, 256, SMEM_TOTAL>>>(x, b1, gamma, beta, Wout, bout, out);
}

// round 12
// speedup vs baseline: 1.5481x; 1.5481x over previous
#include <cuda_runtime.h>
#include <cuda_fp16.h>
#include <cstdint>

#define KC      32              // k elems per chunk
#define NCH     16              // 512 / 32
#define MT      64              // rows per CTA
#define STR     80              // smem row stride bytes (32 fp16 = 64B + 16 pad)
#define AH_OFF  0               // A hi: 64*80 = 5120
#define AL_OFF  5120            // A lo: 64*80 = 5120
#define BH_OFF  10240           // B hi: 512*80 = 40960
#define STG_SZ  51200
#define STAGE0  6144            // after b1/gamma/beta (1536 floats)
#define SMEM_TOTAL (STAGE0 + 2 * STG_SZ)

__device__ unsigned short g_W1h[512 * 512];

__global__ void split_w_kernel(const float* __restrict__ W1) {
    int i = blockIdx.x * 256 + threadIdx.x;
    g_W1h[i] = __half_as_ushort(__float2half_rn(W1[i]));
}

__device__ __forceinline__ uint32_t smem_u32(const void* p) {
    uint32_t a;
    asm("{ .reg .u64 t; cvta.to.shared.u64 t, %1; cvt.u32.u64 %0, t; }" : "=r"(a) : "l"(p));
    return a;
}
__device__ __forceinline__ void ldsm4(uint32_t* r, uint32_t a) {
    asm volatile("ldmatrix.sync.aligned.m8n8.x4.shared.b16 {%0,%1,%2,%3}, [%4];"
                 : "=r"(r[0]), "=r"(r[1]), "=r"(r[2]), "=r"(r[3]) : "r"(a));
}
__device__ __forceinline__ void mma16816(float* c, const uint32_t* a, const uint32_t* b) {
    asm volatile("mma.sync.aligned.m16n8k16.row.col.f32.f16.f16.f32 "
                 "{%0,%1,%2,%3}, {%4,%5,%6,%7}, {%8,%9}, {%0,%1,%2,%3};"
                 : "+f"(c[0]), "+f"(c[1]), "+f"(c[2]), "+f"(c[3])
                 : "r"(a[0]), "r"(a[1]), "r"(a[2]), "r"(a[3]), "r"(b[0]), "r"(b[1]));
}
__device__ __forceinline__ void cp16(uint32_t dst, const void* src) {
    asm volatile("cp.async.ca.shared.global [%0], [%1], 16;"
                 :: "r"(dst), "l"(__cvta_generic_to_global(src)));
}
// split 8 floats into fp16 hi + fp16 lo (x - hi)
__device__ __forceinline__ void cv8(const float4& va, const float4& vb,
                                    uint32_t* hi, uint32_t* lo) {
    float v[8] = {va.x, va.y, va.z, va.w, vb.x, vb.y, vb.z, vb.w};
#pragma unroll
    for (int e = 0; e < 4; ++e) {
        __half h0 = __float2half_rn(v[2*e]);
        __half h1 = __float2half_rn(v[2*e+1]);
        __half l0 = __float2half_rn(v[2*e]   - __half2float(h0));
        __half l1 = __float2half_rn(v[2*e+1] - __half2float(h1));
        hi[e] = ((uint32_t)__half_as_ushort(h1) << 16) | __half_as_ushort(h0);
        lo[e] = ((uint32_t)__half_as_ushort(l1) << 16) | __half_as_ushort(l0);
    }
}

__global__ void __launch_bounds__(256, 1)
hmma_head(const float* __restrict__ x,  const float* __restrict__ b1,
          const float* __restrict__ gamma, const float* __restrict__ beta,
          const float* __restrict__ Wout, const float* __restrict__ bout,
          float* __restrict__ out) {
    extern __shared__ char sm[];
    const uint32_t sbase = smem_u32(sm);
    const int tid  = threadIdx.x;
    const int lane = tid & 31;
    const int wid  = tid >> 5;
    const int wm   = wid & 1;          // 2 M-warps
    const int wn   = wid >> 1;         // 4 N-warps
    const int rowbase = blockIdx.x * MT;

    float* bgb = (float*)sm;           // b1[512] gamma[512] beta[512]
    for (int i = tid; i < 512; i += 256) {
        bgb[i]        = b1[i];
        bgb[512 + i]  = gamma[i];
        bgb[1024 + i] = beta[i];
    }

    // this thread's A-load duty: row ar, k-quarter aq (8 floats)
    const int ar = tid >> 2, aq = tid & 3;
    const int arg = rowbase + ar;
    const float* xrow = x + (((size_t)((arg >> 9) * 513 + (arg & 511))) << 9) + aq * 8;

    // ---- prologue: chunk 0 into stage 0 ----
    {
        float4 xa = *(const float4*)(xrow);
        float4 xb = *(const float4*)(xrow + 4);
        uint32_t hi[4], lo[4];
        cv8(xa, xb, hi, lo);
        *(uint4*)(sm + STAGE0 + AH_OFF + ar * STR + aq * 16) = *(uint4*)hi;
        *(uint4*)(sm + STAGE0 + AL_OFF + ar * STR + aq * 16) = *(uint4*)lo;
#pragma unroll
        for (int it = 0; it < 8; ++it) {
            int idx = tid + it * 256;
            int row = idx >> 2, q = idx & 3;
            cp16(sbase + STAGE0 + BH_OFF + row * STR + q * 16, g_W1h + row * 512 + q * 8);
        }
        asm volatile("cp.async.commit_group;");
        asm volatile("cp.async.wait_group 0;");
        __syncthreads();
    }

    float acc[2][16][4];
#pragma unroll
    for (int i = 0; i < 2; ++i)
#pragma unroll
        for (int j = 0; j < 16; ++j)
#pragma unroll
            for (int e = 0; e < 4; ++e) acc[i][j][e] = 0.f;

    const uint32_t aoff  = (uint32_t)((lane & 15) * STR + (lane >> 4) * 16) + wm * 32 * STR;
    // B ldsm4: m0/m1 = n-rows 0-7 (k0-7, k8-15); m2/m3 = n-rows 8-15
    const uint32_t b4off = (uint32_t)((lane & 7) * STR + ((lane >> 3) & 1) * 16
                                      + (lane >> 4) * 8 * STR) + wn * 128 * STR;

#pragma unroll 1
    for (int c = 0; c < NCH; ++c) {
        const uint32_t stg  = STAGE0 + (uint32_t)(c & 1) * STG_SZ;
        const uint32_t nstg = STAGE0 + (uint32_t)((c & 1) ^ 1) * STG_SZ;
        float4 nxa, nxb;
        if (c < NCH - 1) {
            const int k0n = (c + 1) * KC;
            nxa = *(const float4*)(xrow + k0n);
            nxb = *(const float4*)(xrow + k0n + 4);
#pragma unroll
            for (int it = 0; it < 8; ++it) {
                int idx = tid + it * 256;
                int row = idx >> 2, q = idx & 3;
                cp16(sbase + nstg + BH_OFF + row * STR + q * 16,
                     g_W1h + row * 512 + k0n + q * 8);
            }
            asm volatile("cp.async.commit_group;");
        }

        // ---- compute on stg: 2 passes so each acc reuse is 32 MMAs apart ----
#pragma unroll
        for (int ks = 0; ks < 2; ++ks) {
            uint32_t ah0[4], ah1[4], al0[4], al1[4];
            const uint32_t ab = sbase + stg + aoff + ks * 32;
            ldsm4(ah0, ab + AH_OFF);
            ldsm4(ah1, ab + AH_OFF + 16 * STR);
            ldsm4(al0, ab + AL_OFF);
            ldsm4(al1, ab + AL_OFF + 16 * STR);

            const uint32_t bb = sbase + stg + b4off + ks * 32 + BH_OFF;
            uint32_t bf[2][4];

            // pass 0: xh * Wh
            ldsm4(bf[0], bb);
#pragma unroll
            for (int jj = 0; jj < 8; ++jj) {
                const int cur = jj & 1, nxt = cur ^ 1;
                if (jj < 7) ldsm4(bf[nxt], bb + (uint32_t)(jj + 1) * (16 * STR));
                mma16816(acc[0][2*jj],   ah0, &bf[cur][0]);
                mma16816(acc[1][2*jj],   ah1, &bf[cur][0]);
                mma16816(acc[0][2*jj+1], ah0, &bf[cur][2]);
                mma16816(acc[1][2*jj+1], ah1, &bf[cur][2]);
            }
            // pass 1: xl * Wh
            ldsm4(bf[0], bb);
#pragma unroll
            for (int jj = 0; jj < 8; ++jj) {
                const int cur = jj & 1, nxt = cur ^ 1;
                if (jj < 7) ldsm4(bf[nxt], bb + (uint32_t)(jj + 1) * (16 * STR));
                mma16816(acc[0][2*jj],   al0, &bf[cur][0]);
                mma16816(acc[1][2*jj],   al1, &bf[cur][0]);
                mma16816(acc[0][2*jj+1], al0, &bf[cur][2]);
                mma16816(acc[1][2*jj+1], al1, &bf[cur][2]);
            }
        }

        if (c < NCH - 1) {
            uint32_t hi[4], lo[4];
            cv8(nxa, nxb, hi, lo);
            *(uint4*)(sm + nstg + AH_OFF + ar * STR + aq * 16) = *(uint4*)hi;
            *(uint4*)(sm + nstg + AL_OFF + ar * STR + aq * 16) = *(uint4*)lo;
        }
        asm volatile("cp.async.wait_group 0;");
        __syncthreads();
    }

    // ---- fused epilogue ----
    float2* stats = (float2*)(sm + STAGE0);          // [4][64]
    float2* munrs = (float2*)(sm + STAGE0 + 2048);   // [64]
    float*  pp    = (float*)(sm + STAGE0 + 2560);    // [4][64]

    float sums[4], ssqs[4];
#pragma unroll
    for (int idx = 0; idx < 4; ++idx) {
        const int i = idx >> 1, half = idx & 1;
        float s = 0.f, ss = 0.f;
#pragma unroll
        for (int j = 0; j < 16; ++j) {
            const int cc = wn * 128 + j * 8 + (lane & 3) * 2;
            float h0 = acc[i][j][half * 2 + 0] + bgb[cc];
            float h1 = acc[i][j][half * 2 + 1] + bgb[cc + 1];
            s += h0 + h1;
            ss += h0 * h0 + h1 * h1;
        }
        s  += __shfl_xor_sync(0xffffffffu, s, 1);  s  += __shfl_xor_sync(0xffffffffu, s, 2);
        ss += __shfl_xor_sync(0xffffffffu, ss, 1); ss += __shfl_xor_sync(0xffffffffu, ss, 2);
        sums[idx] = s; ssqs[idx] = ss;
    }
    if ((lane & 3) == 0) {
        const int q = lane >> 2;
#pragma unroll
        for (int idx = 0; idx < 4; ++idx) {
            const int r = wm * 32 + (idx >> 1) * 16 + (idx & 1) * 8 + q;
            stats[wn * 64 + r] = make_float2(sums[idx], ssqs[idx]);
        }
    }
    __syncthreads();
    if (tid < 64) {
        float s = 0.f, ss = 0.f;
#pragma unroll
        for (int w = 0; w < 4; ++w) { float2 v = stats[w * 64 + tid]; s += v.x; ss += v.y; }
        const float mu = s * (1.f / 512.f);
        const float var = ss * (1.f / 512.f) - mu * mu;
        munrs[tid] = make_float2(mu, rsqrtf(var + 1e-5f));
    }
    __syncthreads();

#pragma unroll
    for (int idx = 0; idx < 4; ++idx) {
        const int i = idx >> 1, half = idx & 1;
        const int r = wm * 32 + (idx >> 1) * 16 + (idx & 1) * 8 + (lane >> 2);
        const float2 mr = munrs[r];
        const int tt = (rowbase + r) & 511;
        const float* wrow = Wout + (((size_t)tt) << 9);
        float p = 0.f;
#pragma unroll
        for (int j = 0; j < 16; ++j) {
            const int cc = wn * 128 + j * 8 + (lane & 3) * 2;
            const float2 wo = *(const float2*)(wrow + cc);
            float h0 = acc[i][j][half * 2 + 0] + bgb[cc];
            float h1 = acc[i][j][half * 2 + 1] + bgb[cc + 1];
            float y0 = fmaxf((h0 - mr.x) * mr.y * bgb[512 + cc]     + bgb[1024 + cc],     0.f);
            float y1 = fmaxf((h1 - mr.x) * mr.y * bgb[512 + cc + 1] + bgb[1024 + cc + 1], 0.f);
            p += y0 * wo.x + y1 * wo.y;
        }
        p += __shfl_xor_sync(0xffffffffu, p, 1);
        p += __shfl_xor_sync(0xffffffffu, p, 2);
        if ((lane & 3) == 0) pp[wn * 64 + r] = p;
    }
    __syncthreads();
    if (tid < 64) {
        const int rg = rowbase + tid;
        const int tt = rg & 511;
        out[rg] = pp[tid] + pp[64 + tid] + pp[128 + tid] + pp[192 + tid] + bout[tt];
    }
}

extern "C" void kernel_launch(void* const* d_in, const int* in_sizes, int n_in,
                              void* d_out, int out_size) {
    const float* x     = (const float*)d_in[0];
    const float* W1    = (const float*)d_in[1];
    const float* b1    = (const float*)d_in[2];
    const float* gamma = (const float*)d_in[3];
    const float* beta  = (const float*)d_in[4];
    const float* Wout  = (const float*)d_in[5];
    const float* bout  = (const float*)d_in[6];
    float* out = (float*)d_out;

    cudaFuncSetAttribute(hmma_head, cudaFuncAttributeMaxDynamicSharedMemorySize, SMEM_TOTAL);

    split_w_kernel<<<1024, 256>>>(W1);
    hmma_head<<<131072 / MT, 256, SMEM_TOTAL>>>(x, b1, gamma, beta, Wout, bout, out);
}